// round 10
// baseline (speedup 1.0000x reference)
#include <cuda_runtime.h>
#include <stdint.h>

#define BB   8
#define NN   8192
#define CIN  64
#define COUT 128
#define MM   2048
#define KNN  16
#define ROWS (BB*NN)            // 65536
#define Y_SIZE ((size_t)BB*MM*COUT)

#define FPS_G       8           // blocks per batch
#define FPS_PPB     (NN/FPS_G)  // 1024 points per block
#define FPS_THREADS 256
#define FPS_PT      4           // points per thread

// ---------------- scratch (static device globals; no allocations) ----------------
__device__ float g_h[(size_t)ROWS*COUT];     // raw h = x @ W^T  (32 MB)
__device__ int   g_nbr[(size_t)BB*MM*KNN];   // kNN indices
__device__ float g_psum[256*COUT];
__device__ float g_psq [256*COUT];
__device__ float g_scale[COUT];
__device__ float g_shift[COUT];
// FPS cross-block mailboxes: parity-double-buffered 16B records + gen words
__device__ __align__(16) float4 g_fslot[BB][2][FPS_G];   // {val, x, y, z}
__device__ unsigned g_fgen[BB][FPS_G];   // monotonic within a call; RESET by bnstat2

// -------- packed f32x2 helpers (sm_100+; per-lane bits == scalar rn ops) --------
#define ADD_F32X2(out, a, b) \
    asm("add.rn.f32x2 %0, %1, %2;" : "=l"(out) : "l"(a), "l"(b))
#define MUL_F32X2(out, a, b) \
    asm("mul.rn.f32x2 %0, %1, %2;" : "=l"(out) : "l"(a), "l"(b))
#define PACK_F32X2(out, lo, hi) \
    asm("mov.b64 %0, {%1, %2};" : "=l"(out) : "f"(lo), "f"(hi))
#define UNPACK_F32X2(lo, hi, in) \
    asm("mov.b64 {%0, %1}, %2;" : "=f"(lo), "=f"(hi) : "l"(in))

#define REDUX_MAX_U32(out, in) \
    asm("redux.sync.max.u32 %0, %1, 0xffffffff;" : "=r"(out) : "r"(in))
#define REDUX_MIN_U32(out, in) \
    asm("redux.sync.min.u32 %0, %1, 0xffffffff;" : "=r"(out) : "r"(in))

// =============================== FPS ===============================
// 64 blocks = 8 batches x 8 groups; each block owns 1024 contiguous points
// (4/thread, packed f32x2; distance bits identical to XLA: dx=X+(-lx),
// d=(dx^2+dy^2)+dz^2, separate rn ops — trajectory bit-exact since R3).
// Per iteration:
//   in-block : redux.max(val) + redux.min(index) per warp; leaders STS to
//              parity-buffered smem; ONE __syncthreads; all warps redux the
//              8 leader slots -> block winner (val,idx).
//   publish  : owner thread STG.128 {val,x,y,z} into g_fslot[b][j&1][g],
//              __threadfence, then g_fgen[b][g]=j.
//   combine  : lanes 0..7 poll g_fgen[b][lane] >= j (monotonic within the
//              call => no deadlock; max skew 1 iter => parity buffer safe),
//              LDG.128 the record, redux over the 8 values; lowest winning
//              slot = lowest global index. shfl coords from winner lane.
// g_fgen is zeroed by bnstat2 (runs before fps in-stream) EVERY call, so
// graph replays are deterministic. All 64 blocks are wave-1 resident.
__global__ void __launch_bounds__(FPS_THREADS, 1)
fps_kernel(const float* __restrict__ p1, float* __restrict__ p2out) {
    __shared__ unsigned swv[2][8], swi[2][8];
    const int bg  = blockIdx.x;
    const int b   = bg >> 3;
    const int g   = bg & 7;
    const int tid = threadIdx.x;
    const int lane = tid & 31;
    const int wid  = tid >> 5;
    const float* p = p1 + (size_t)b*NN*3;
    const int pbase = g*FPS_PPB + tid*FPS_PT;    // global index of this thread's 1st point

    float MD[FPS_PT];
    unsigned long long Xp[FPS_PT/2], Yp[FPS_PT/2], Zp[FPS_PT/2];
    {
        float buf[FPS_PT*3];
        const float4* pv = (const float4*)(p + (size_t)pbase*3);
        #pragma unroll
        for (int i = 0; i < FPS_PT*3/4; i++) {
            float4 v = pv[i];
            buf[i*4+0]=v.x; buf[i*4+1]=v.y; buf[i*4+2]=v.z; buf[i*4+3]=v.w;
        }
        #pragma unroll
        for (int k = 0; k < FPS_PT; k++) MD[k] = 1e10f;
        #pragma unroll
        for (int i = 0; i < FPS_PT/2; i++) {
            PACK_F32X2(Xp[i], buf[6*i+0], buf[6*i+3]);
            PACK_F32X2(Yp[i], buf[6*i+1], buf[6*i+4]);
            PACK_F32X2(Zp[i], buf[6*i+2], buf[6*i+5]);
        }
    }
    float lx = p[0], ly = p[1], lz = p[2];
    if (g == 0 && tid == 0) {
        size_t o0 = (size_t)b*MM*3;
        p2out[o0+0]=lx; p2out[o0+1]=ly; p2out[o0+2]=lz;
    }

    for (int j = 1; j < MM; j++) {
        float nlx = -lx, nly = -ly, nlz = -lz;
        unsigned long long nlx2, nly2, nlz2;
        PACK_F32X2(nlx2, nlx, nlx);
        PACK_F32X2(nly2, nly, nly);
        PACK_F32X2(nlz2, nlz, nlz);

        #pragma unroll
        for (int i = 0; i < FPS_PT/2; i++) {
            unsigned long long dx, dy, dz, sx, sy, sz, s, d;
            ADD_F32X2(dx, Xp[i], nlx2);          // X + (-lx) == X - lx (bitwise)
            ADD_F32X2(dy, Yp[i], nly2);
            ADD_F32X2(dz, Zp[i], nlz2);
            MUL_F32X2(sx, dx, dx);
            MUL_F32X2(sy, dy, dy);
            MUL_F32X2(sz, dz, dz);
            ADD_F32X2(s,  sx, sy);               // (dx^2+dy^2)
            ADD_F32X2(d,  s,  sz);               // ... + dz^2
            float d0, d1; UNPACK_F32X2(d0, d1, d);
            MD[2*i]   = fminf(MD[2*i],   d0);
            MD[2*i+1] = fminf(MD[2*i+1], d1);
        }

        // thread-local argmax over 4 (lowest k on ties)
        float bv = fmaxf(fmaxf(MD[0],MD[1]), fmaxf(MD[2],MD[3]));
        int bi = 3;
        if (MD[2] == bv) bi = 2;
        if (MD[1] == bv) bi = 1;
        if (MD[0] == bv) bi = 0;
        unsigned bvb = __float_as_uint(bv);      // dist >= 0: float order == u32 order

        // warp reduce: max value, then min index among ties
        unsigned wmax; REDUX_MAX_U32(wmax, bvb);
        unsigned cand = (bvb == wmax) ? (unsigned)(pbase + bi) : 0xFFFFFFFFu;
        unsigned widx; REDUX_MIN_U32(widx, cand);
        if (lane == 0) { swv[j & 1][wid] = wmax; swi[j & 1][wid] = widx; }
        __syncthreads();                          // only in-block barrier

        // block reduce (all warps redundantly over 8 leader slots)
        unsigned v  = (lane < 8) ? swv[j & 1][lane] : 0u;
        unsigned bval; REDUX_MAX_U32(bval, v);
        unsigned ci = (lane < 8 && v == bval) ? swi[j & 1][lane] : 0xFFFFFFFFu;
        unsigned bidx; REDUX_MIN_U32(bidx, ci);   // block winner global index

        // owner publishes {val,x,y,z} then gen
        if (tid == (int)((bidx - (unsigned)(g*FPS_PPB)) >> 2)) {
            int kk = (int)(bidx & 3u);
            float cx = 0.f, cy = 0.f, cz = 0.f;
            #pragma unroll
            for (int k = FPS_PT-1; k >= 0; k--) {
                if (kk == k) {
                    float a0, a1;
                    UNPACK_F32X2(a0, a1, Xp[k>>1]); cx = (k & 1) ? a1 : a0;
                    UNPACK_F32X2(a0, a1, Yp[k>>1]); cy = (k & 1) ? a1 : a0;
                    UNPACK_F32X2(a0, a1, Zp[k>>1]); cz = (k & 1) ? a1 : a0;
                }
            }
            g_fslot[b][j & 1][g] = make_float4(__uint_as_float(bval), cx, cy, cz);
            __threadfence();
            asm volatile("st.volatile.global.u32 [%0], %1;"
                         :: "l"(&g_fgen[b][g]), "r"((unsigned)j) : "memory");
        }

        // cross-block combine: poll 8 gens, read records, pick winner
        unsigned rvb = 0; float rx = 0.f, ry = 0.f, rz = 0.f;
        if (lane < 8) {
            const unsigned* gp = &g_fgen[b][lane];
            unsigned gen;
            do {
                asm volatile("ld.volatile.global.u32 %0, [%1];" : "=r"(gen) : "l"(gp));
            } while (gen < (unsigned)j);          // monotonic: >= j accepts
            const float4* rp = &g_fslot[b][j & 1][lane];
            float ra, rb, rc, rd;
            asm volatile("ld.volatile.global.v4.f32 {%0,%1,%2,%3}, [%4];"
                         : "=f"(ra), "=f"(rb), "=f"(rc), "=f"(rd) : "l"(rp));
            rvb = __float_as_uint(ra); rx = rb; ry = rc; rz = rd;
        }
        __syncwarp();
        unsigned gm; REDUX_MAX_U32(gm, rvb);
        unsigned ball = __ballot_sync(0xffffffffu, (lane < 8) && rvb == gm);
        int src = __ffs((int)ball) - 1;           // lowest slot = lowest index
        lx = __shfl_sync(0xffffffffu, rx, src);
        ly = __shfl_sync(0xffffffffu, ry, src);
        lz = __shfl_sync(0xffffffffu, rz, src);
        if (g == 0 && wid == 0 && lane == 0) {
            size_t o2 = (size_t)(b*MM + j)*3;
            p2out[o2] = lx; p2out[o2+1] = ly; p2out[o2+2] = lz;
        }
    }
}

// =============================== GEMM ===============================
// h[r][o] = sum_c x[r][c]*W[o][c], exact fp32, k-ascending FFMA chain from a
// zero accumulator — bit-matches cuBLAS SGEMM's inner loop.
__global__ void __launch_bounds__(256)
gemm_kernel(const float* __restrict__ x, const float* __restrict__ W) {
    extern __shared__ float sm[];
    float* xs = sm;                // [128][65] padded
    float* ws = sm + 128*65;       // [64][128] = W^T
    const int tid = threadIdx.x;
    const size_t rb = (size_t)blockIdx.x * 128;
    const float* gx = x + rb*CIN;

    for (int i = tid; i < 128*CIN; i += 256) {
        int r = i >> 6, c = i & 63;
        xs[r*65 + c] = gx[i];
    }
    for (int i = tid; i < COUT*CIN; i += 256) {
        int o = i >> 6, c = i & 63;
        ws[c*COUT + o] = W[i];
    }
    __syncthreads();

    const int tx = tid & 15, ty = tid >> 4;
    const int r0 = ty*8, o0 = tx*8;
    float acc[8][8];
    #pragma unroll
    for (int i = 0; i < 8; i++)
        #pragma unroll
        for (int j = 0; j < 8; j++) acc[i][j] = 0.f;

    for (int c = 0; c < CIN; c++) {
        float a[8];
        #pragma unroll
        for (int i = 0; i < 8; i++) a[i] = xs[(r0+i)*65 + c];
        float4 b0 = *(const float4*)&ws[c*COUT + o0];
        float4 b1 = *(const float4*)&ws[c*COUT + o0 + 4];
        float bb[8] = {b0.x,b0.y,b0.z,b0.w,b1.x,b1.y,b1.z,b1.w};
        #pragma unroll
        for (int i = 0; i < 8; i++)
            #pragma unroll
            for (int j = 0; j < 8; j++) acc[i][j] = __fmaf_rn(a[i], bb[j], acc[i][j]);
    }
    #pragma unroll
    for (int i = 0; i < 8; i++) {
        float* out = &g_h[(rb + r0 + i)*COUT + o0];
        *(float4*)out       = make_float4(acc[i][0],acc[i][1],acc[i][2],acc[i][3]);
        *(float4*)(out + 4) = make_float4(acc[i][4],acc[i][5],acc[i][6],acc[i][7]);
    }
}

// ====================== BN stats (deterministic 2-stage) ======================
__global__ void __launch_bounds__(128) bnstat1() {
    const int c = threadIdx.x;
    const int blk = blockIdx.x;                  // 256 blocks x 256 rows
    const float* base = g_h + (size_t)blk*256*COUT;
    float s = 0.f, q = 0.f;
    for (int r = 0; r < 256; r++) {
        float v = base[(size_t)r*COUT + c];
        s += v; q = __fmaf_rn(v, v, q);
    }
    g_psum[blk*COUT + c] = s;
    g_psq [blk*COUT + c] = q;
}

// one block per channel; 256 threads each grab one partial, warp+smem tree.
// Block 0 ALSO resets the FPS mailbox generation words (runs before fps in
// the stream every call -> graph replays are deterministic).
__global__ void __launch_bounds__(256)
bnstat2(const float* __restrict__ gamma, const float* __restrict__ beta) {
    const int c = blockIdx.x;
    const int t = threadIdx.x;
    if (c == 0 && t < BB*FPS_G) ((unsigned*)g_fgen)[t] = 0u;   // reset mailboxes
    __shared__ double ss[8], sq[8];
    double s = (double)g_psum[t*COUT + c];
    double q = (double)g_psq [t*COUT + c];
    #pragma unroll
    for (int o = 16; o; o >>= 1) {
        s += __shfl_down_sync(0xffffffffu, s, o);
        q += __shfl_down_sync(0xffffffffu, q, o);
    }
    if ((t & 31) == 0) { ss[t >> 5] = s; sq[t >> 5] = q; }
    __syncthreads();
    if (t == 0) {
        double S = 0.0, Q = 0.0;
        #pragma unroll
        for (int w = 0; w < 8; w++) { S += ss[w]; Q += sq[w]; }
        double mean = S / (double)ROWS;
        double var  = Q / (double)ROWS - mean*mean;
        double inv  = 1.0 / sqrt(var + 1e-5);
        float sc = (float)inv * gamma[c];
        g_scale[c] = sc;
        g_shift[c] = __fmaf_rn(-(float)mean, sc, beta[c]);
    }
}

// =============================== kNN ===============================
// One warp per query. Per-lane register top-16 (packed sortable keys),
// warp merge by 16x min-extraction.
// d2 = (s2 - 2*dot) + s1 with:
//   s1, s2 : separate rn mul/add  (XLA fused elementwise+reduce — no FMA)
//   dot    : FFMA chain, k-ascending from rn(x*qx)  (cuBLAS SGEMM inner loop)
__device__ __forceinline__ unsigned f2key(float d) {
    unsigned u = __float_as_uint(d);
    return u ^ ((u >> 31) ? 0xFFFFFFFFu : 0x80000000u);
}

__global__ void __launch_bounds__(256)
knn_kernel(const float* __restrict__ p1, const float* __restrict__ p2) {
    extern __shared__ float sm[];
    float* px = sm; float* py = sm+NN; float* pz = sm+2*NN; float* s1 = sm+3*NN;
    const int tid = threadIdx.x;
    const int b  = blockIdx.x >> 8;       // 256 blocks per batch
    const int mg = blockIdx.x & 255;
    const float* p = p1 + (size_t)b*NN*3;

    for (int i = tid; i < NN*3; i += 256) {
        float v = p[i];
        int pt = i / 3, d = i - pt*3;
        (d == 0 ? px : (d == 1 ? py : pz))[pt] = v;
    }
    __syncthreads();
    for (int i = tid; i < NN; i += 256)
        s1[i] = __fadd_rn(__fadd_rn(__fmul_rn(px[i],px[i]), __fmul_rn(py[i],py[i])), __fmul_rn(pz[i],pz[i]));
    __syncthreads();

    const int w = tid >> 5, lane = tid & 31;
    const int m = mg*8 + w;
    const size_t qi = (size_t)b*MM + m;
    const float qx = p2[qi*3], qy = p2[qi*3+1], qz = p2[qi*3+2];
    const float s2 = __fadd_rn(__fadd_rn(__fmul_rn(qx,qx), __fmul_rn(qy,qy)), __fmul_rn(qz,qz));

    const unsigned long long INITK =
        ((unsigned long long)0xFF7FFFFFu << 32) | 0xFFFFFFFFu;
    unsigned long long bk[KNN];
    #pragma unroll
    for (int k = 0; k < KNN; k++) bk[k] = INITK;
    float thr = 3.4e38f;

    for (int i = lane; i < NN; i += 32) {
        float dot = __fmaf_rn(pz[i], qz, __fmaf_rn(py[i], qy, __fmul_rn(px[i], qx)));
        float d   = __fadd_rn(__fsub_rn(s2, __fmul_rn(2.0f, dot)), s1[i]);
        if (d < thr) {   // equal -> keep earlier index (top_k stability)
            unsigned long long nk = ((unsigned long long)f2key(d) << 32) | (unsigned)i;
            unsigned long long mk = 0; int mp = 0;
            #pragma unroll
            for (int k = 0; k < KNN; k++) if (bk[k] > mk) { mk = bk[k]; mp = k; }
            #pragma unroll
            for (int k = 0; k < KNN; k++) if (k == mp) bk[k] = nk;
            mk = 0;
            #pragma unroll
            for (int k = 0; k < KNN; k++) if (bk[k] > mk) mk = bk[k];
            unsigned hv = (unsigned)(mk >> 32);
            hv = (hv & 0x80000000u) ? (hv ^ 0x80000000u) : ~hv;
            thr = __uint_as_float(hv);
        }
    }

    unsigned long long res = 0;
    for (int r = 0; r < KNN; r++) {
        unsigned long long lm = 0xFFFFFFFFFFFFFFFFull;
        #pragma unroll
        for (int k = 0; k < KNN; k++) if (bk[k] < lm) lm = bk[k];
        unsigned long long wm = lm;
        #pragma unroll
        for (int o = 16; o; o >>= 1) {
            unsigned long long t = __shfl_xor_sync(0xffffffffu, wm, o);
            if (t < wm) wm = t;
        }
        if (lm == wm) {
            #pragma unroll
            for (int k = 0; k < KNN; k++) if (bk[k] == wm) bk[k] = 0xFFFFFFFFFFFFFFFFull;
        }
        if (lane == r) res = wm;
    }
    if (lane < KNN) g_nbr[qi*KNN + lane] = (int)(res & 0xFFFFFFFFu);
}

// =========================== gather + BN + ReLU + max ===========================
__global__ void __launch_bounds__(256)
gather_kernel(float* __restrict__ y) {
    const int tid = threadIdx.x;
    const int w = tid >> 5, lane = tid & 31;
    const int q = blockIdx.x*8 + w;              // global (b,m) id
    const int b = q >> 11;
    const int* nb = g_nbr + (size_t)q*KNN;
    const float4 sc = *(const float4*)&g_scale[lane*4];
    const float4 sh = *(const float4*)&g_shift[lane*4];
    const float* hb = g_h + (size_t)b*NN*COUT;

    float4 acc = make_float4(-3.4e38f,-3.4e38f,-3.4e38f,-3.4e38f);
    #pragma unroll
    for (int k = 0; k < KNN; k++) {
        int n = nb[k];
        float4 v = *(const float4*)&hb[(size_t)n*COUT + lane*4];
        float f;
        f = fmaxf(__fmaf_rn(v.x, sc.x, sh.x), 0.f); acc.x = fmaxf(acc.x, f);
        f = fmaxf(__fmaf_rn(v.y, sc.y, sh.y), 0.f); acc.y = fmaxf(acc.y, f);
        f = fmaxf(__fmaf_rn(v.z, sc.z, sh.z), 0.f); acc.z = fmaxf(acc.z, f);
        f = fmaxf(__fmaf_rn(v.w, sc.w, sh.w), 0.f); acc.w = fmaxf(acc.w, f);
    }
    *(float4*)&y[(size_t)q*COUT + lane*4] = acc;
}

// =============================== launch ===============================
// Order keeps fps_kernel in the ncu-captured slot (index 3):
// gemm -> bnstat1 -> bnstat2(+mailbox reset) -> fps -> knn -> gather.
extern "C" void kernel_launch(void* const* d_in, const int* in_sizes, int n_in,
                              void* d_out, int out_size) {
    const float* x     = (const float*)d_in[0];
    const float* p1    = (const float*)d_in[1];
    const float* W     = (const float*)d_in[2];
    const float* gamma = (const float*)d_in[3];
    const float* beta  = (const float*)d_in[4];
    float* y  = (float*)d_out;
    float* p2 = y + Y_SIZE;

    const int KNN_SMEM  = 4*NN*4;          // 128 KB
    const int GEMM_SMEM = (128*65 + 64*128)*4;

    cudaFuncSetAttribute(knn_kernel,  cudaFuncAttributeMaxDynamicSharedMemorySize, KNN_SMEM);
    cudaFuncSetAttribute(gemm_kernel, cudaFuncAttributeMaxDynamicSharedMemorySize, GEMM_SMEM);

    gemm_kernel<<<ROWS/128, 256, GEMM_SMEM>>>(x, W);
    bnstat1<<<256, 128>>>();
    bnstat2<<<COUT, 256>>>(gamma, beta);
    fps_kernel<<<BB*FPS_G, FPS_THREADS>>>(p1, p2);   // 64 blocks, all wave-1
    knn_kernel<<<BB*(MM/8), 256, KNN_SMEM>>>(p1, p2);
    gather_kernel<<<(BB*MM)/8, 256>>>(y);
}

// round 11
// speedup vs baseline: 3.0537x; 3.0537x over previous
#include <cuda_runtime.h>
#include <stdint.h>

#define BB   8
#define NN   8192
#define CIN  64
#define COUT 128
#define MM   2048
#define KNN  16
#define ROWS (BB*NN)            // 65536
#define Y_SIZE ((size_t)BB*MM*COUT)

#define FPS_G       8           // CTAs per cluster (= per batch)
#define FPS_PPB     (NN/FPS_G)  // 1024 points per CTA
#define FPS_THREADS 256
#define FPS_PT      4           // points per thread

// ---------------- scratch (static device globals; no allocations) ----------------
__device__ float g_h[(size_t)ROWS*COUT];     // raw h = x @ W^T  (32 MB)
__device__ int   g_nbr[(size_t)BB*MM*KNN];   // kNN indices
__device__ float g_psum[256*COUT];
__device__ float g_psq [256*COUT];
__device__ float g_scale[COUT];
__device__ float g_shift[COUT];

// -------- packed f32x2 helpers (sm_100+; per-lane bits == scalar rn ops) --------
#define ADD_F32X2(out, a, b) \
    asm("add.rn.f32x2 %0, %1, %2;" : "=l"(out) : "l"(a), "l"(b))
#define MUL_F32X2(out, a, b) \
    asm("mul.rn.f32x2 %0, %1, %2;" : "=l"(out) : "l"(a), "l"(b))
#define PACK_F32X2(out, lo, hi) \
    asm("mov.b64 %0, {%1, %2};" : "=l"(out) : "f"(lo), "f"(hi))
#define UNPACK_F32X2(lo, hi, in) \
    asm("mov.b64 {%0, %1}, %2;" : "=f"(lo), "=f"(hi) : "l"(in))

#define REDUX_MAX_U32(out, in) \
    asm("redux.sync.max.u32 %0, %1, 0xffffffff;" : "=r"(out) : "r"(in))
#define REDUX_MIN_U32(out, in) \
    asm("redux.sync.min.u32 %0, %1, 0xffffffff;" : "=r"(out) : "r"(in))

__device__ __forceinline__ uint32_t smem_u32(const void* p) {
    uint32_t a;
    asm("{ .reg .u64 t; cvta.to.shared.u64 t, %1; cvt.u32.u64 %0, t; }"
        : "=r"(a) : "l"(p));
    return a;
}

// =============================== FPS ===============================
// 8 clusters (one per batch) x 8 CTAs; each CTA owns 1024 contiguous points
// (4/thread, packed f32x2; distance bits identical to XLA: dx=X+(-lx),
// d=(dx^2+dy^2)+dz^2, separate rn ops — trajectory bit-exact since R3).
// Per iteration:
//   in-CTA  : redux.max(val)+redux.min(idx) per warp; leaders STS (parity);
//             ONE __syncthreads; all warps redux 8 leader slots -> (val,idx).
//   publish : winning thread writes {val,x,y,z} into slots[j&1][rank] of ALL
//             8 cluster CTAs via mapa + st.shared::cluster.v4 (DSMEM).
//   sync    : ONE cluster.sync (arrive releases the DSMEM stores).
//   combine : every warp reads the 8 LOCAL smem records, redux over values,
//             lowest winning slot = lowest global index; shfl coords.
// Parity double-buffer + the sync chain separates reader(j) from writer(j+2).
// No cross-call state -> graph replays deterministic.
__global__ void __launch_bounds__(FPS_THREADS, 1) __cluster_dims__(FPS_G, 1, 1)
fps_kernel(const float* __restrict__ p1, float* __restrict__ p2out) {
    __shared__ __align__(16) float4 slots[2][FPS_G];
    __shared__ unsigned swv[2][8], swi[2][8];
    const int bg  = blockIdx.x;
    const int b   = bg >> 3;
    const int g   = bg & 7;                      // == cluster_ctarank
    const int tid = threadIdx.x;
    const int lane = tid & 31;
    const int wid  = tid >> 5;
    const float* p = p1 + (size_t)b*NN*3;
    const int pbase = g*FPS_PPB + tid*FPS_PT;

    float MD[FPS_PT];
    unsigned long long Xp[FPS_PT/2], Yp[FPS_PT/2], Zp[FPS_PT/2];
    {
        float buf[FPS_PT*3];
        const float4* pv = (const float4*)(p + (size_t)pbase*3);
        #pragma unroll
        for (int i = 0; i < FPS_PT*3/4; i++) {
            float4 v = pv[i];
            buf[i*4+0]=v.x; buf[i*4+1]=v.y; buf[i*4+2]=v.z; buf[i*4+3]=v.w;
        }
        #pragma unroll
        for (int k = 0; k < FPS_PT; k++) MD[k] = 1e10f;
        #pragma unroll
        for (int i = 0; i < FPS_PT/2; i++) {
            PACK_F32X2(Xp[i], buf[6*i+0], buf[6*i+3]);
            PACK_F32X2(Yp[i], buf[6*i+1], buf[6*i+4]);
            PACK_F32X2(Zp[i], buf[6*i+2], buf[6*i+5]);
        }
    }
    float lx = p[0], ly = p[1], lz = p[2];
    if (g == 0 && tid == 0) {
        size_t o0 = (size_t)b*MM*3;
        p2out[o0+0]=lx; p2out[o0+1]=ly; p2out[o0+2]=lz;
    }
    const uint32_t myslot0 = smem_u32(&slots[0][g]);
    const uint32_t myslot1 = smem_u32(&slots[1][g]);

    for (int j = 1; j < MM; j++) {
        float nlx = -lx, nly = -ly, nlz = -lz;
        unsigned long long nlx2, nly2, nlz2;
        PACK_F32X2(nlx2, nlx, nlx);
        PACK_F32X2(nly2, nly, nly);
        PACK_F32X2(nlz2, nlz, nlz);

        #pragma unroll
        for (int i = 0; i < FPS_PT/2; i++) {
            unsigned long long dx, dy, dz, sx, sy, sz, s, d;
            ADD_F32X2(dx, Xp[i], nlx2);          // X + (-lx) == X - lx (bitwise)
            ADD_F32X2(dy, Yp[i], nly2);
            ADD_F32X2(dz, Zp[i], nlz2);
            MUL_F32X2(sx, dx, dx);
            MUL_F32X2(sy, dy, dy);
            MUL_F32X2(sz, dz, dz);
            ADD_F32X2(s,  sx, sy);               // (dx^2+dy^2)
            ADD_F32X2(d,  s,  sz);               // ... + dz^2
            float d0, d1; UNPACK_F32X2(d0, d1, d);
            MD[2*i]   = fminf(MD[2*i],   d0);
            MD[2*i+1] = fminf(MD[2*i+1], d1);
        }

        // thread-local argmax over 4 (lowest k on ties)
        float bv = fmaxf(fmaxf(MD[0],MD[1]), fmaxf(MD[2],MD[3]));
        int bi = 3;
        if (MD[2] == bv) bi = 2;
        if (MD[1] == bv) bi = 1;
        if (MD[0] == bv) bi = 0;
        unsigned bvb = __float_as_uint(bv);      // dist >= 0: float order == u32 order

        // warp reduce: max value, then min index among ties
        unsigned wmax; REDUX_MAX_U32(wmax, bvb);
        unsigned cand = (bvb == wmax) ? (unsigned)(pbase + bi) : 0xFFFFFFFFu;
        unsigned widx; REDUX_MIN_U32(widx, cand);
        if (lane == 0) { swv[j & 1][wid] = wmax; swi[j & 1][wid] = widx; }
        __syncthreads();

        // CTA reduce (all warps redundantly over 8 leader slots)
        unsigned v  = (lane < 8) ? swv[j & 1][lane] : 0u;
        unsigned bval; REDUX_MAX_U32(bval, v);
        unsigned ci = (lane < 8 && v == bval) ? swi[j & 1][lane] : 0xFFFFFFFFu;
        unsigned bidx; REDUX_MIN_U32(bidx, ci);   // CTA winner global index

        // winner thread publishes {val,x,y,z} into ALL cluster CTAs' slots
        if (tid == (int)((bidx - (unsigned)(g*FPS_PPB)) >> 2)) {
            int kk = (int)(bidx & 3u);
            float cx = 0.f, cy = 0.f, cz = 0.f;
            #pragma unroll
            for (int k = FPS_PT-1; k >= 0; k--) {
                if (kk == k) {
                    float a0, a1;
                    UNPACK_F32X2(a0, a1, Xp[k>>1]); cx = (k & 1) ? a1 : a0;
                    UNPACK_F32X2(a0, a1, Yp[k>>1]); cy = (k & 1) ? a1 : a0;
                    UNPACK_F32X2(a0, a1, Zp[k>>1]); cz = (k & 1) ? a1 : a0;
                }
            }
            uint32_t myslot = (j & 1) ? myslot1 : myslot0;
            float fv = __uint_as_float(bval);
            #pragma unroll
            for (int r = 0; r < FPS_G; r++) {
                uint32_t raddr;
                asm("mapa.shared::cluster.u32 %0, %1, %2;"
                    : "=r"(raddr) : "r"(myslot), "r"(r));
                asm volatile("st.shared::cluster.v4.f32 [%0], {%1,%2,%3,%4};"
                             :: "r"(raddr), "f"(fv), "f"(cx), "f"(cy), "f"(cz)
                             : "memory");
            }
        }

        // one cluster barrier: arrive releases DSMEM stores, wait acquires
        asm volatile("barrier.cluster.arrive.aligned;" ::: "memory");
        asm volatile("barrier.cluster.wait.aligned;" ::: "memory");

        // combine 8 LOCAL records (every warp redundantly)
        unsigned rvb = 0; float rx = 0.f, ry = 0.f, rz = 0.f;
        if (lane < FPS_G) {
            float4 rec = slots[j & 1][lane];
            rvb = __float_as_uint(rec.x); rx = rec.y; ry = rec.z; rz = rec.w;
        }
        __syncwarp();
        unsigned gm; REDUX_MAX_U32(gm, rvb);
        unsigned ball = __ballot_sync(0xffffffffu, (lane < FPS_G) && rvb == gm);
        int src = __ffs((int)ball) - 1;           // lowest slot = lowest index
        lx = __shfl_sync(0xffffffffu, rx, src);
        ly = __shfl_sync(0xffffffffu, ry, src);
        lz = __shfl_sync(0xffffffffu, rz, src);
        if (g == 0 && tid == 0) {
            size_t o2 = (size_t)(b*MM + j)*3;
            p2out[o2] = lx; p2out[o2+1] = ly; p2out[o2+2] = lz;
        }
    }
}

// =============================== GEMM ===============================
// h[r][o] = sum_c x[r][c]*W[o][c], exact fp32, k-ascending FFMA chain from a
// zero accumulator — bit-matches cuBLAS SGEMM's inner loop.
__global__ void __launch_bounds__(256)
gemm_kernel(const float* __restrict__ x, const float* __restrict__ W) {
    extern __shared__ float sm[];
    float* xs = sm;                // [128][65] padded
    float* ws = sm + 128*65;       // [64][128] = W^T
    const int tid = threadIdx.x;
    const size_t rb = (size_t)blockIdx.x * 128;
    const float* gx = x + rb*CIN;

    for (int i = tid; i < 128*CIN; i += 256) {
        int r = i >> 6, c = i & 63;
        xs[r*65 + c] = gx[i];
    }
    for (int i = tid; i < COUT*CIN; i += 256) {
        int o = i >> 6, c = i & 63;
        ws[c*COUT + o] = W[i];
    }
    __syncthreads();

    const int tx = tid & 15, ty = tid >> 4;
    const int r0 = ty*8, o0 = tx*8;
    float acc[8][8];
    #pragma unroll
    for (int i = 0; i < 8; i++)
        #pragma unroll
        for (int j = 0; j < 8; j++) acc[i][j] = 0.f;

    for (int c = 0; c < CIN; c++) {
        float a[8];
        #pragma unroll
        for (int i = 0; i < 8; i++) a[i] = xs[(r0+i)*65 + c];
        float4 b0 = *(const float4*)&ws[c*COUT + o0];
        float4 b1 = *(const float4*)&ws[c*COUT + o0 + 4];
        float bb[8] = {b0.x,b0.y,b0.z,b0.w,b1.x,b1.y,b1.z,b1.w};
        #pragma unroll
        for (int i = 0; i < 8; i++)
            #pragma unroll
            for (int j = 0; j < 8; j++) acc[i][j] = __fmaf_rn(a[i], bb[j], acc[i][j]);
    }
    #pragma unroll
    for (int i = 0; i < 8; i++) {
        float* out = &g_h[(rb + r0 + i)*COUT + o0];
        *(float4*)out       = make_float4(acc[i][0],acc[i][1],acc[i][2],acc[i][3]);
        *(float4*)(out + 4) = make_float4(acc[i][4],acc[i][5],acc[i][6],acc[i][7]);
    }
}

// ====================== BN stats (deterministic 2-stage) ======================
__global__ void __launch_bounds__(128) bnstat1() {
    const int c = threadIdx.x;
    const int blk = blockIdx.x;                  // 256 blocks x 256 rows
    const float* base = g_h + (size_t)blk*256*COUT;
    float s = 0.f, q = 0.f;
    for (int r = 0; r < 256; r++) {
        float v = base[(size_t)r*COUT + c];
        s += v; q = __fmaf_rn(v, v, q);
    }
    g_psum[blk*COUT + c] = s;
    g_psq [blk*COUT + c] = q;
}

// one block per channel; 256 threads each grab one partial, warp+smem tree
__global__ void __launch_bounds__(256)
bnstat2(const float* __restrict__ gamma, const float* __restrict__ beta) {
    const int c = blockIdx.x;
    const int t = threadIdx.x;
    __shared__ double ss[8], sq[8];
    double s = (double)g_psum[t*COUT + c];
    double q = (double)g_psq [t*COUT + c];
    #pragma unroll
    for (int o = 16; o; o >>= 1) {
        s += __shfl_down_sync(0xffffffffu, s, o);
        q += __shfl_down_sync(0xffffffffu, q, o);
    }
    if ((t & 31) == 0) { ss[t >> 5] = s; sq[t >> 5] = q; }
    __syncthreads();
    if (t == 0) {
        double S = 0.0, Q = 0.0;
        #pragma unroll
        for (int w = 0; w < 8; w++) { S += ss[w]; Q += sq[w]; }
        double mean = S / (double)ROWS;
        double var  = Q / (double)ROWS - mean*mean;
        double inv  = 1.0 / sqrt(var + 1e-5);
        float sc = (float)inv * gamma[c];
        g_scale[c] = sc;
        g_shift[c] = __fmaf_rn(-(float)mean, sc, beta[c]);
    }
}

// =============================== kNN ===============================
// One warp per query. Per-lane register top-16 (packed sortable keys),
// warp merge by 16x min-extraction.
// d2 = (s2 - 2*dot) + s1 with:
//   s1, s2 : separate rn mul/add  (XLA fused elementwise+reduce — no FMA)
//   dot    : FFMA chain, k-ascending from rn(x*qx)  (cuBLAS SGEMM inner loop)
__device__ __forceinline__ unsigned f2key(float d) {
    unsigned u = __float_as_uint(d);
    return u ^ ((u >> 31) ? 0xFFFFFFFFu : 0x80000000u);
}

__global__ void __launch_bounds__(256)
knn_kernel(const float* __restrict__ p1, const float* __restrict__ p2) {
    extern __shared__ float sm[];
    float* px = sm; float* py = sm+NN; float* pz = sm+2*NN; float* s1 = sm+3*NN;
    const int tid = threadIdx.x;
    const int b  = blockIdx.x >> 8;       // 256 blocks per batch
    const int mg = blockIdx.x & 255;
    const float* p = p1 + (size_t)b*NN*3;

    for (int i = tid; i < NN*3; i += 256) {
        float v = p[i];
        int pt = i / 3, d = i - pt*3;
        (d == 0 ? px : (d == 1 ? py : pz))[pt] = v;
    }
    __syncthreads();
    for (int i = tid; i < NN; i += 256)
        s1[i] = __fadd_rn(__fadd_rn(__fmul_rn(px[i],px[i]), __fmul_rn(py[i],py[i])), __fmul_rn(pz[i],pz[i]));
    __syncthreads();

    const int w = tid >> 5, lane = tid & 31;
    const int m = mg*8 + w;
    const size_t qi = (size_t)b*MM + m;
    const float qx = p2[qi*3], qy = p2[qi*3+1], qz = p2[qi*3+2];
    const float s2 = __fadd_rn(__fadd_rn(__fmul_rn(qx,qx), __fmul_rn(qy,qy)), __fmul_rn(qz,qz));

    const unsigned long long INITK =
        ((unsigned long long)0xFF7FFFFFu << 32) | 0xFFFFFFFFu;
    unsigned long long bk[KNN];
    #pragma unroll
    for (int k = 0; k < KNN; k++) bk[k] = INITK;
    float thr = 3.4e38f;

    for (int i = lane; i < NN; i += 32) {
        float dot = __fmaf_rn(pz[i], qz, __fmaf_rn(py[i], qy, __fmul_rn(px[i], qx)));
        float d   = __fadd_rn(__fsub_rn(s2, __fmul_rn(2.0f, dot)), s1[i]);
        if (d < thr) {   // equal -> keep earlier index (top_k stability)
            unsigned long long nk = ((unsigned long long)f2key(d) << 32) | (unsigned)i;
            unsigned long long mk = 0; int mp = 0;
            #pragma unroll
            for (int k = 0; k < KNN; k++) if (bk[k] > mk) { mk = bk[k]; mp = k; }
            #pragma unroll
            for (int k = 0; k < KNN; k++) if (k == mp) bk[k] = nk;
            mk = 0;
            #pragma unroll
            for (int k = 0; k < KNN; k++) if (bk[k] > mk) mk = bk[k];
            unsigned hv = (unsigned)(mk >> 32);
            hv = (hv & 0x80000000u) ? (hv ^ 0x80000000u) : ~hv;
            thr = __uint_as_float(hv);
        }
    }

    unsigned long long res = 0;
    for (int r = 0; r < KNN; r++) {
        unsigned long long lm = 0xFFFFFFFFFFFFFFFFull;
        #pragma unroll
        for (int k = 0; k < KNN; k++) if (bk[k] < lm) lm = bk[k];
        unsigned long long wm = lm;
        #pragma unroll
        for (int o = 16; o; o >>= 1) {
            unsigned long long t = __shfl_xor_sync(0xffffffffu, wm, o);
            if (t < wm) wm = t;
        }
        if (lm == wm) {
            #pragma unroll
            for (int k = 0; k < KNN; k++) if (bk[k] == wm) bk[k] = 0xFFFFFFFFFFFFFFFFull;
        }
        if (lane == r) res = wm;
    }
    if (lane < KNN) g_nbr[qi*KNN + lane] = (int)(res & 0xFFFFFFFFu);
}

// =========================== gather + BN + ReLU + max ===========================
__global__ void __launch_bounds__(256)
gather_kernel(float* __restrict__ y) {
    const int tid = threadIdx.x;
    const int w = tid >> 5, lane = tid & 31;
    const int q = blockIdx.x*8 + w;              // global (b,m) id
    const int b = q >> 11;
    const int* nb = g_nbr + (size_t)q*KNN;
    const float4 sc = *(const float4*)&g_scale[lane*4];
    const float4 sh = *(const float4*)&g_shift[lane*4];
    const float* hb = g_h + (size_t)b*NN*COUT;

    float4 acc = make_float4(-3.4e38f,-3.4e38f,-3.4e38f,-3.4e38f);
    #pragma unroll
    for (int k = 0; k < KNN; k++) {
        int n = nb[k];
        float4 v = *(const float4*)&hb[(size_t)n*COUT + lane*4];
        float f;
        f = fmaxf(__fmaf_rn(v.x, sc.x, sh.x), 0.f); acc.x = fmaxf(acc.x, f);
        f = fmaxf(__fmaf_rn(v.y, sc.y, sh.y), 0.f); acc.y = fmaxf(acc.y, f);
        f = fmaxf(__fmaf_rn(v.z, sc.z, sh.z), 0.f); acc.z = fmaxf(acc.z, f);
        f = fmaxf(__fmaf_rn(v.w, sc.w, sh.w), 0.f); acc.w = fmaxf(acc.w, f);
    }
    *(float4*)&y[(size_t)q*COUT + lane*4] = acc;
}

// =============================== launch ===============================
// Order keeps fps_kernel in the ncu-captured slot (index 3):
// gemm -> bnstat1 -> bnstat2 -> fps(clusters) -> knn -> gather.
extern "C" void kernel_launch(void* const* d_in, const int* in_sizes, int n_in,
                              void* d_out, int out_size) {
    const float* x     = (const float*)d_in[0];
    const float* p1    = (const float*)d_in[1];
    const float* W     = (const float*)d_in[2];
    const float* gamma = (const float*)d_in[3];
    const float* beta  = (const float*)d_in[4];
    float* y  = (float*)d_out;
    float* p2 = y + Y_SIZE;

    const int KNN_SMEM  = 4*NN*4;          // 128 KB
    const int GEMM_SMEM = (128*65 + 64*128)*4;

    cudaFuncSetAttribute(knn_kernel,  cudaFuncAttributeMaxDynamicSharedMemorySize, KNN_SMEM);
    cudaFuncSetAttribute(gemm_kernel, cudaFuncAttributeMaxDynamicSharedMemorySize, GEMM_SMEM);

    gemm_kernel<<<ROWS/128, 256, GEMM_SMEM>>>(x, W);
    bnstat1<<<256, 128>>>();
    bnstat2<<<COUT, 256>>>(gamma, beta);
    fps_kernel<<<BB*FPS_G, FPS_THREADS>>>(p1, p2);   // 8 clusters x 8 CTAs
    knn_kernel<<<BB*(MM/8), 256, KNN_SMEM>>>(p1, p2);
    gather_kernel<<<(BB*MM)/8, 256>>>(y);
}